// round 8
// baseline (speedup 1.0000x reference)
#include <cuda_runtime.h>
#include <cuda_bf16.h>
#include <cstdint>

#define FULLM 0xffffffffu
#define DINLINE __device__ __forceinline__

constexpr int NN = 150000, CC = 256, LL = 50000, KTOP = 200;
constexpr int NU = NN - LL;
constexpr int SEGP = 1376;             // 43 chunks of 32 rows
constexpr int NSEGP = 73;              // 73 * 1376 = 100448 >= NU
constexpr int CHKP = 43;
constexpr int NPAD = NSEGP * SEGP;     // padded unlabeled rows
constexpr int NIMG = LL + NPAD;        // 150448 image rows (>= NN, pad zero)
// ptx mma kernel smem: per stage ph(16896)+pl(16896)+xh(8704)+xl(8704)=51200, x2
constexpr int SMEM_PTX = 102400;
// xpt mma kernel smem: A h+l double buffer (2*20480) + B double buffer (2*20480)
constexpr int SMEM_XPT = 81920;

// ---------------- scratch (device globals; no allocation allowed) ------------
__device__ float g_prob[(size_t)NU * CC];
__device__ int   g_cls[NN];
__device__ float g_rnorm[NN];
__device__ float g_psum[CC * CC];
__device__ float g_protos[CC * CC];
__device__ float g_S[CC * CC];
__device__ float g_colsum[CC];
__device__ int   g_cntall[CC];
__device__ int   g_cntlab[CC];
__device__ int   g_off[CC];
__device__ int   g_fill[CC];
__device__ int   g_rowidx[LL];
// protoN as bf16 hi/lo smem-image: [chunk 8][hl 2][class 256][40 shorts (80B pitch)]
__device__ unsigned short g_Bimg[8 * 2 * 256 * 40];
// masked-p bf16 hi/lo images [NU-row][256] (pad rows stay zero)
__device__ __align__(16) unsigned short g_Ph[(size_t)NPAD * CC];
__device__ __align__(16) unsigned short g_Pl[(size_t)NPAD * CC];
// raw-x bf16 hi/lo images, GLOBAL row index [NIMG][256] (pad rows zero)
__device__ __align__(16) unsigned short g_Xbh[(size_t)NIMG * CC];
__device__ __align__(16) unsigned short g_Xbl[(size_t)NIMG * CC];

// ---------------- helpers ----------------------------------------------------
DINLINE float block_reduce_sum(float v) {
    __shared__ float red[8];
    __shared__ float tot;
    for (int o = 16; o; o >>= 1) v += __shfl_xor_sync(FULLM, v, o);
    if ((threadIdx.x & 31) == 0) red[threadIdx.x >> 5] = v;
    __syncthreads();
    if (threadIdx.x < 32) {
        float s = (threadIdx.x < 8) ? red[threadIdx.x] : 0.f;
        for (int o = 4; o; o >>= 1) s += __shfl_xor_sync(FULLM, s, o);
        if (threadIdx.x == 0) tot = s;
    }
    __syncthreads();
    return tot;
}
DINLINE unsigned fkey(float v) {
    unsigned u = __float_as_uint(v);
    return (u & 0x80000000u) ? ~u : (u | 0x80000000u);
}
DINLINE uint32_t smem_u32(const void* p) {
    uint32_t a;
    asm("{ .reg .u64 t; cvta.to.shared.u64 t, %1; cvt.u32.u64 %0, t; }"
        : "=r"(a) : "l"(p));
    return a;
}
DINLINE uint32_t bf2pk(float hi, float lo) {   // hi -> upper 16 bits
    uint32_t u;
    asm("cvt.rn.bf16x2.f32 %0, %1, %2;" : "=r"(u) : "f"(hi), "f"(lo));
    return u;
}
DINLINE void bsplit(float v, unsigned short& h, unsigned short& l) {
    __nv_bfloat16 hb = __float2bfloat16_rn(v);
    unsigned short hs = __bfloat16_as_ushort(hb);
    float hf = __uint_as_float((uint32_t)hs << 16);
    __nv_bfloat16 lb = __float2bfloat16_rn(v - hf);
    h = hs;
    l = __bfloat16_as_ushort(lb);
}
DINLINE void cpasync16(uint32_t dst, const void* src) {
    asm volatile("cp.async.ca.shared.global [%0], [%1], 16;"
                 :: "r"(dst), "l"(src));
}
#define CP_COMMIT() asm volatile("cp.async.commit_group;" ::: "memory")
#define CP_WAIT0()  asm volatile("cp.async.wait_group 0;" ::: "memory")
#define CP_WAIT1()  asm volatile("cp.async.wait_group 1;" ::: "memory")

DINLINE void ldm_x4(uint32_t* r, uint32_t addr) {
    asm volatile("ldmatrix.sync.aligned.m8n8.x4.shared.b16 {%0,%1,%2,%3}, [%4];"
                 : "=r"(r[0]), "=r"(r[1]), "=r"(r[2]), "=r"(r[3]) : "r"(addr));
}
DINLINE void ldm_x2(uint32_t* r, uint32_t addr) {
    asm volatile("ldmatrix.sync.aligned.m8n8.x2.shared.b16 {%0,%1}, [%2];"
                 : "=r"(r[0]), "=r"(r[1]) : "r"(addr));
}
DINLINE void ldmT_x4(uint32_t* r, uint32_t addr) {
    asm volatile("ldmatrix.sync.aligned.m8n8.x4.trans.shared.b16 {%0,%1,%2,%3}, [%4];"
                 : "=r"(r[0]), "=r"(r[1]), "=r"(r[2]), "=r"(r[3]) : "r"(addr));
}
DINLINE void ldmT_x2(uint32_t* r, uint32_t addr) {
    asm volatile("ldmatrix.sync.aligned.m8n8.x2.trans.shared.b16 {%0,%1}, [%2];"
                 : "=r"(r[0]), "=r"(r[1]) : "r"(addr));
}
DINLINE void mma_bf16(float* c, const uint32_t* a, const uint32_t* b) {
    asm volatile(
        "mma.sync.aligned.m16n8k16.row.col.f32.bf16.bf16.f32 "
        "{%0,%1,%2,%3}, {%4,%5,%6,%7}, {%8,%9}, {%0,%1,%2,%3};"
        : "+f"(c[0]), "+f"(c[1]), "+f"(c[2]), "+f"(c[3])
        : "r"(a[0]), "r"(a[1]), "r"(a[2]), "r"(a[3]), "r"(b[0]), "r"(b[1]));
}

// ---------------- kernel 0: zero accumulators --------------------------------
__global__ void zero_k() {
    int i = blockIdx.x * blockDim.x + threadIdx.x;
    if (i < CC * CC) g_S[i] = 0.f;
    if (i < CC) { g_colsum[i] = 0.f; g_cntall[i] = 0; g_cntlab[i] = 0; }
}

// ---------------- kernel 1: class id, rnorm, hist + x bf16 image (ALL rows) --
__global__ void prep_k(const float* __restrict__ x, const float* __restrict__ labels) {
    __shared__ int s_all[CC], s_lab[CC];
    for (int i = threadIdx.x; i < CC; i += blockDim.x) { s_all[i] = 0; s_lab[i] = 0; }
    __syncthreads();
    int warp = threadIdx.x >> 5, lane = threadIdx.x & 31;
    int wpb = blockDim.x >> 5;
    for (int row = blockIdx.x * wpb + warp; row < NN; row += gridDim.x * wpb) {
        const float* lr = labels + (size_t)row * CC;
        int myc = -1;
        #pragma unroll
        for (int j = 0; j < 8; j++) {
            int c = lane + 32 * j;
            if (lr[c] > 0.5f) myc = c;
        }
        int cls = __reduce_max_sync(FULLM, myc);
        const float4* xr = (const float4*)(x + (size_t)row * CC);
        float ss = 0.f;
        float4 v[2];
        #pragma unroll
        for (int j = 0; j < 2; j++) {
            v[j] = xr[lane + 32 * j];
            ss += v[j].x * v[j].x + v[j].y * v[j].y + v[j].z * v[j].z + v[j].w * v[j].w;
        }
        for (int o = 16; o; o >>= 1) ss += __shfl_xor_sync(FULLM, ss, o);
        if (lane == 0) {
            g_cls[row] = cls;
            g_rnorm[row] = rsqrtf(fmaxf(ss, 1e-12f));
            atomicAdd(&s_all[cls], 1);
            if (row < LL) atomicAdd(&s_lab[cls], 1);
        }
        // write raw-x bf16 split image (all rows, global index)
        size_t ur = (size_t)row * CC;
        #pragma unroll
        for (int j = 0; j < 2; j++) {
            int fb = 4 * (lane + 32 * j);
            uint32_t h0 = bf2pk(v[j].y, v[j].x), h1 = bf2pk(v[j].w, v[j].z);
            float f0 = __uint_as_float(h0 << 16);
            float f1 = __uint_as_float(h0 & 0xffff0000u);
            float f2 = __uint_as_float(h1 << 16);
            float f3 = __uint_as_float(h1 & 0xffff0000u);
            uint32_t l0 = bf2pk(v[j].y - f1, v[j].x - f0);
            uint32_t l1 = bf2pk(v[j].w - f3, v[j].z - f2);
            *(uint2*)(g_Xbh + ur + fb) = make_uint2(h0, h1);
            *(uint2*)(g_Xbl + ur + fb) = make_uint2(l0, l1);
        }
    }
    __syncthreads();
    for (int i = threadIdx.x; i < CC; i += blockDim.x) {
        if (s_all[i]) atomicAdd(&g_cntall[i], s_all[i]);
        if (s_lab[i]) atomicAdd(&g_cntlab[i], s_lab[i]);
    }
}

// ---------------- per-class labeled sums: scan -> scatter -> gather ----------
__global__ void scan_k() {     // 1 block, 256 threads: exclusive scan of cntlab
    __shared__ int tmp[CC];
    int c = threadIdx.x;
    int v = g_cntlab[c];
    tmp[c] = v;
    __syncthreads();
    for (int off = 1; off < CC; off <<= 1) {
        int t = (c >= off) ? tmp[c - off] : 0;
        __syncthreads();
        tmp[c] += t;
        __syncthreads();
    }
    int excl = tmp[c] - v;
    g_off[c] = excl;
    g_fill[c] = excl;
}
__global__ void scatter_k() {
    int row = blockIdx.x * 256 + threadIdx.x;
    if (row < LL) {
        int cls = g_cls[row];
        int pos = atomicAdd(&g_fill[cls], 1);
        g_rowidx[pos] = row;
    }
}
__global__ void paccum_k(const float* __restrict__ x) {
    __shared__ int sidx[256];
    int c = blockIdx.x, f = threadIdx.x;
    int n = g_cntlab[c], o = g_off[c];
    float acc = 0.f;
    for (int base = 0; base < n; base += 256) {
        int m = min(256, n - base);
        __syncthreads();
        if (f < m) sidx[f] = g_rowidx[o + base + f];
        __syncthreads();
        for (int i = 0; i < m; i++)
            acc += x[(size_t)sidx[i] * CC + f];
    }
    g_psum[c * CC + f] = acc;
}

// ---------------- write protoN split (bf16 hi/lo) into image -----------------
DINLINE void write_bimg(int c, int f, float v) {
    unsigned short h, l;
    bsplit(v, h, l);
    int ck = f >> 5, kl = f & 31;
    g_Bimg[((ck * 2 + 0) * 256 + c) * 40 + kl] = h;
    g_Bimg[((ck * 2 + 1) * 256 + c) * 40 + kl] = l;
}

// ---------------- kernel: protos + normalized protoN split -------------------
__global__ void pfin_k() {
    int c = blockIdx.x, f = threadIdx.x;
    float v = g_psum[c * CC + f] / (float)g_cntall[c];
    g_protos[c * CC + f] = v;
    float tot = block_reduce_sum(v * v);
    write_bimg(c, f, v * rsqrtf(fmaxf(tot, 1e-12f)));
}

// ---------------- mma.sync bf16x3 GEMM: OUT[n][c] = rnorm[n]*(X[n].pN[c]) ----
// A (hi+lo) from pre-split bf16 images, cp.async double-buffered.
__global__ void __launch_bounds__(256, 2)
gemm_mma_k(float* __restrict__ OUT, int imgoff, int nrows) {
    extern __shared__ char dsm[];
    __shared__ float s_rn[128];
    float* __restrict__ O = OUT ? OUT : g_prob;

    const int tid = threadIdx.x, lane = tid & 31, wid = tid >> 5;
    const int wm = wid >> 2, wn = wid & 3;
    const int n0 = blockIdx.x * 128;
    const int c0 = blockIdx.y * 128;

    const uint32_t uA0 = smem_u32(dsm);
    const uint32_t uA1 = uA0 + 20480;
    const uint32_t uB0 = uA1 + 20480;
    const uint32_t uB1 = uB0 + 20480;

    if (tid < 128) {
        int r = imgoff + n0 + tid;
        s_rn[tid] = (n0 + tid < nrows) ? g_rnorm[r] : 0.f;
    }

    const int a_row = (lane & 7) + 8 * ((lane >> 3) & 1);
    const int a_kb  = 16 * (lane >> 4);
    const int b_row = lane & 7;
    const int b_kb  = 16 * ((lane >> 3) & 1);
    const uint32_t aoff = (uint32_t)((64 * wm + a_row) * 80 + a_kb);
    const uint32_t bofs = (uint32_t)((32 * wn + b_row) * 80 + b_kb);

    float acc[4][4][4];
    #pragma unroll
    for (int i = 0; i < 4; i++)
        #pragma unroll
        for (int j = 0; j < 4; j++)
            #pragma unroll
            for (int q = 0; q < 4; q++) acc[i][j][q] = 0.f;

    auto stageA = [&](uint32_t ub, int ckn) {
        #pragma unroll
        for (int s = 0; s < 4; s++) {
            int t = tid + 256 * s;
            int img = t >> 9, rem = t & 511, r = rem >> 2, pc = rem & 3;
            const unsigned short* src = (img ? g_Xbl : g_Xbh)
                + (size_t)(imgoff + n0 + r) * CC + ckn * 32 + pc * 8;
            cpasync16(ub + (uint32_t)img * 10240u + (uint32_t)(r * 80 + pc * 16), src);
        }
    };
    auto stageB = [&](uint32_t ub, int ckn) {
        const char* srcH = (const char*)g_Bimg + (size_t)((ckn * 2 + 0) * 256 + c0) * 80;
        const char* srcL = (const char*)g_Bimg + (size_t)((ckn * 2 + 1) * 256 + c0) * 80;
        #pragma unroll
        for (int s = 0; s < 5; s++) {
            int j = tid + 256 * s;
            if (j < 640) cpasync16(ub + 16 * j, srcH + 16 * j);
            else         cpasync16(ub + 10240 + 16 * (j - 640), srcL + 16 * (j - 640));
        }
    };

    stageA(uA0, 0); stageB(uB0, 0); CP_COMMIT();

    for (int ck = 0; ck < 8; ck++) {
        uint32_t uAc = (ck & 1) ? uA1 : uA0;
        uint32_t uBc = (ck & 1) ? uB1 : uB0;
        if (ck < 7) {
            stageA((ck & 1) ? uA0 : uA1, ck + 1);
            stageB((ck & 1) ? uB0 : uB1, ck + 1);
            CP_COMMIT();
            CP_WAIT1();
        } else {
            CP_WAIT0();
        }
        __syncthreads();

        #pragma unroll
        for (int ks = 0; ks < 2; ks++) {
            uint32_t bh[4][2], bl[4][2];
            #pragma unroll
            for (int nf = 0; nf < 4; nf++) {
                ldm_x2(bh[nf], uBc + bofs + nf * 640 + ks * 32);
                ldm_x2(bl[nf], uBc + 10240 + bofs + nf * 640 + ks * 32);
            }
            #pragma unroll
            for (int mf = 0; mf < 4; mf++) {
                uint32_t ah[4], al[4];
                ldm_x4(ah, uAc + aoff + mf * 1280 + ks * 32);
                ldm_x4(al, uAc + 10240 + aoff + mf * 1280 + ks * 32);
                #pragma unroll
                for (int nf = 0; nf < 4; nf++) {
                    mma_bf16(acc[mf][nf], ah, bh[nf]);
                    mma_bf16(acc[mf][nf], al, bh[nf]);
                    mma_bf16(acc[mf][nf], ah, bl[nf]);
                }
            }
        }
        __syncthreads();
    }

    #pragma unroll
    for (int mf = 0; mf < 4; mf++) {
        #pragma unroll
        for (int half = 0; half < 2; half++) {
            int rl = 64 * wm + 16 * mf + (lane >> 2) + 8 * half;
            int grow = n0 + rl;
            if (grow < nrows) {
                float rs = s_rn[rl];
                float* op = O + (size_t)grow * CC + c0 + 32 * wn + 2 * (lane & 3);
                #pragma unroll
                for (int nf = 0; nf < 4; nf++) {
                    float2 v = make_float2(acc[mf][nf][2 * half] * rs,
                                           acc[mf][nf][2 * half + 1] * rs);
                    *(float2*)(op + 8 * nf) = v;
                }
            }
        }
    }
}

// ---------------- kernel: exact per-row top-k -> bf16 split images -----------
__global__ void topk_k() {
    __shared__ float cs[CC];
    for (int i = threadIdx.x; i < CC; i += blockDim.x) cs[i] = 0.f;
    __syncthreads();
    int warp = threadIdx.x >> 5, lane = threadIdx.x & 31;
    for (int row = blockIdx.x * 8 + warp; row < NU; row += gridDim.x * 8) {
        const float* pr = g_prob + (size_t)row * CC;
        float v[8]; unsigned key[8];
        #pragma unroll
        for (int j = 0; j < 8; j++) { v[j] = pr[lane + 32 * j]; key[j] = fkey(v[j]); }
        unsigned T = 0;
        for (int b = 31; b >= 0; b--) {
            unsigned cand = T | (1u << b);
            int cnt = 0;
            #pragma unroll
            for (int j = 0; j < 8; j++) cnt += (key[j] >= cand);
            cnt = (int)__reduce_add_sync(FULLM, (unsigned)cnt);
            if (cnt >= KTOP) T = cand;
        }
        int gt = 0;
        #pragma unroll
        for (int j = 0; j < 8; j++) gt += (key[j] > T);
        gt = (int)__reduce_add_sync(FULLM, (unsigned)gt);
        int r = KTOP - gt;
        int cum = 0;
        #pragma unroll
        for (int j = 0; j < 8; j++) {
            bool eq = (key[j] == T);
            unsigned bal = __ballot_sync(FULLM, eq);
            int pre = cum + __popc(bal & ((1u << lane) - 1u));
            bool keep = (key[j] > T) || (eq && pre < r);
            cum += __popc(bal);
            float o = keep ? v[j] : 0.f;
            unsigned short h, l;
            bsplit(o, h, l);
            size_t idx = (size_t)row * CC + lane + 32 * j;
            g_Ph[idx] = h;
            g_Pl[idx] = l;
            if (o != 0.f) atomicAdd(&cs[lane + 32 * j], o);
        }
    }
    __syncthreads();
    float c = cs[threadIdx.x];
    if (c != 0.f) atomicAdd(&g_colsum[threadIdx.x], c);
}

// ---------------- split-K bf16x3 mma GEMM: S[c][f] += sum_r p[r][c]*x[r][f] --
__global__ void __launch_bounds__(512, 1)
gemm_ptx_mma_k() {
    extern __shared__ char dsm[];
    const uint32_t uS0 = smem_u32(dsm);
    const uint32_t uS1 = uS0 + 51200;

    const int tid = threadIdx.x, lane = tid & 31, wid = tid >> 5;
    const int wm = wid >> 2, wn = wid & 3;
    const int f0 = blockIdx.y * 128;
    const int R0 = blockIdx.x * SEGP;

    auto stage = [&](uint32_t ub, int ck) {
        int r0 = R0 + ck * 32;
        #pragma unroll
        for (int s = 0; s < 6; s++) {
            int t = tid + 512 * s;
            if (t < 2048) {
                int img = t >> 10;
                int r = (t >> 5) & 31;
                int piece = t & 31;
                const char* src = (const char*)(img ? g_Pl : g_Ph)
                                  + (size_t)(r0 + r) * 512 + piece * 16;
                cpasync16(ub + img * 16896 + r * 528 + piece * 16, src);
            } else {
                int t2 = t - 2048;
                int img = t2 >> 9;
                int r = (t2 >> 4) & 31;
                int piece = t2 & 15;
                const char* src = (const char*)(img ? g_Xbl : g_Xbh)
                                  + (size_t)(LL + r0 + r) * 512 + f0 * 2 + piece * 16;
                cpasync16(ub + 33792 + img * 8704 + r * 272 + piece * 16, src);
            }
        }
        CP_COMMIT();
    };

    const int krA = (lane & 7) + 8 * ((lane >> 4) & 1);
    const int cmA = 64 * wm + 8 * ((lane >> 3) & 1);
    const int krB = (lane & 7) + 8 * ((lane >> 3) & 1);
    const uint32_t aoff = (uint32_t)(krA * 528 + 2 * cmA);
    const uint32_t boff = (uint32_t)(krB * 272 + 2 * (32 * wn));

    float acc[4][4][4];
    #pragma unroll
    for (int i = 0; i < 4; i++)
        #pragma unroll
        for (int j = 0; j < 4; j++)
            #pragma unroll
            for (int q = 0; q < 4; q++) acc[i][j][q] = 0.f;

    stage(uS0, 0);

    for (int ck = 0; ck < CHKP; ck++) {
        if (ck + 1 < CHKP) {
            stage((ck & 1) ? uS0 : uS1, ck + 1);
            CP_WAIT1();
        } else {
            CP_WAIT0();
        }
        __syncthreads();

        uint32_t uP = (ck & 1) ? uS1 : uS0;
        uint32_t uX = uP + 33792;
        #pragma unroll
        for (int ks = 0; ks < 2; ks++) {
            uint32_t bh[4][2], bl[4][2];
            #pragma unroll
            for (int nf = 0; nf < 4; nf++) {
                uint32_t ba = uX + (uint32_t)(ks * 16 * 272) + boff + 2 * (8 * nf);
                ldmT_x2(bh[nf], ba);
                ldmT_x2(bl[nf], ba + 8704);
            }
            #pragma unroll
            for (int mf = 0; mf < 4; mf++) {
                uint32_t aa = uP + (uint32_t)(ks * 16 * 528) + aoff + 2 * (16 * mf);
                uint32_t ah[4], al[4];
                ldmT_x4(ah, aa);
                ldmT_x4(al, aa + 16896);
                #pragma unroll
                for (int nf = 0; nf < 4; nf++) {
                    mma_bf16(acc[mf][nf], ah, bh[nf]);
                    mma_bf16(acc[mf][nf], al, bh[nf]);
                    mma_bf16(acc[mf][nf], ah, bl[nf]);
                }
            }
        }
        __syncthreads();
    }

    #pragma unroll
    for (int mf = 0; mf < 4; mf++) {
        #pragma unroll
        for (int nf = 0; nf < 4; nf++) {
            #pragma unroll
            for (int half = 0; half < 2; half++) {
                int c = 64 * wm + 16 * mf + (lane >> 2) + 8 * half;
                int f = f0 + 32 * wn + 8 * nf + 2 * (lane & 3);
                atomicAdd(&g_S[c * CC + f + 0], acc[mf][nf][2 * half + 0]);
                atomicAdd(&g_S[c * CC + f + 1], acc[mf][nf][2 * half + 1]);
            }
        }
    }
}

// ---------------- kernel: proto update + renorm + split write ----------------
__global__ void pfin2_k() {
    int c = blockIdx.x, f = threadIdx.x;
    float cp = g_colsum[c];
    float denom = cp + (float)g_cntlab[c];
    float pv = g_protos[c * CC + f];
    float nv = pv + g_S[c * CC + f] / denom - (cp / denom) * pv;
    float tot = block_reduce_sum(nv * nv);
    write_bimg(c, f, nv * rsqrtf(fmaxf(tot, 1e-12f)));
}

// ---------------- launch ------------------------------------------------------
extern "C" void kernel_launch(void* const* d_in, const int* in_sizes, int n_in,
                              void* d_out, int out_size) {
    (void)in_sizes; (void)n_in; (void)out_size;
    const float* x = (const float*)d_in[0];
    const float* labels = (const float*)d_in[1];
    float* out = (float*)d_out;

    cudaFuncSetAttribute(gemm_mma_k,
                         cudaFuncAttributeMaxDynamicSharedMemorySize, SMEM_XPT);
    cudaFuncSetAttribute(gemm_ptx_mma_k,
                         cudaFuncAttributeMaxDynamicSharedMemorySize, SMEM_PTX);

    zero_k<<<CC, 256>>>();
    prep_k<<<1480, 256>>>(x, labels);
    scan_k<<<1, 256>>>();
    scatter_k<<<(LL + 255) / 256, 256>>>();
    paccum_k<<<CC, 256>>>(x);
    pfin_k<<<CC, 256>>>();
    gemm_mma_k<<<dim3((NU + 127) / 128, 2), 256, SMEM_XPT>>>(nullptr, LL, NU);
    topk_k<<<1563, 256>>>();
    gemm_ptx_mma_k<<<dim3(NSEGP, 2), 512, SMEM_PTX>>>();
    pfin2_k<<<CC, 256>>>();
    gemm_mma_k<<<dim3((NN + 127) / 128, 2), 256, SMEM_XPT>>>(out, 0, NN);
}